// round 15
// baseline (speedup 1.0000x reference)
#include <cuda_runtime.h>
#include <cuda_fp16.h>
#include <cstdint>
#include <math.h>

#define NN 100000
#define NN_PAD 100096
#define MT16 (NN_PAD / 16)        // 6256 m16 tiles
#define GG 100
#define NE 1000000
#define HH 256
#define TT 4
#define J2H 112                   // 1792/16 n8-tile-pairs for fused h GEMM
#define J2M 48                    // 768/16 for msgs GEMM

// ===================== scratch (device globals) =============================
__device__ float  d_h[(size_t)NN * HH];
__device__ __half d_trans[(size_t)NN_PAD * TT * HH];  // [node][t][256] fp16
__device__ __half d_msgsh[4][(size_t)NN * HH];        // per-step fp16 msgs
__device__ __half d_g1h[(size_t)NN_PAD * 3 * HH];     // fp16 gates (msgs@W)
__device__ __half d_g2h[(size_t)NN_PAD * 3 * HH];     // fp16 gates (h@U)
__device__ uint4  d_hp[(size_t)MT16 * 512];           // permuted fp16 A (h)
__device__ uint4  d_msgsp[(size_t)MT16 * 512];        // permuted fp16 A (msgs)
__device__ uint4  d_BH[(size_t)2 * 16 * J2H * 32];    // permuted fp16 B (tw|U)
__device__ uint4  d_BM[(size_t)2 * 16 * J2M * 32];    // permuted fp16 B (W)
__device__ float  d_biasH[2 * 1792];
__device__ float  d_pe[513 * 256];
__device__ float  d_gate[NN];
__device__ float  d_out2[NN * 2];
__device__ float  d_partial[256];
__device__ float  d_gmax;
__device__ int    d_cum[GG + 1];
__device__ float  d_S[GG];
__device__ float  d_P[GG * 2];

__device__ __forceinline__ uint32_t packh2(float lo, float hi) {
    __half2 h = __floats2half2_rn(lo, hi);
    return *reinterpret_cast<uint32_t*>(&h);
}
__device__ __forceinline__ uint32_t smem_u32(const void* p) {
    uint32_t a;
    asm("{ .reg .u64 t; cvta.to.shared.u64 t, %1; cvt.u32.u64 %0, t; }"
        : "=r"(a) : "l"(p));
    return a;
}

// write 4 consecutive values (row n, cols c..c+3) into fragment layout at dst
__device__ __forceinline__ void store_frag(uint4* dst, int n, int c, float v0,
                                           float v1, float v2, float v3) {
    int i = n >> 4, r = n & 15, kk = c >> 4, cl = c & 15;
    uint32_t comp = ((cl >= 8) ? 8u : 0u) + ((r >= 8) ? 4u : 0u);
    int lane0 = (r & 7) * 4 + ((cl & 7) >> 1);
    char* base = (char*)dst + (((size_t)i * 512 + (size_t)kk * 32) * 16) + comp;
    *(__half2*)(base + (size_t)lane0 * 16)       = __floats2half2_rn(v0, v1);
    *(__half2*)(base + (size_t)(lane0 + 1) * 16) = __floats2half2_rn(v2, v3);
}

// ===================== merged weight prep (1 launch) ========================
#define NBH (2 * 16 * J2H * 32)   // 114688
#define NBM (2 * 16 * J2M * 32)   // 49152
#define NPREP (NBH + NBM + 2 * 1792)

__device__ __forceinline__ float bvalH(const float* tw, const float* U,
                                       int l, int k, int n) {
    if (n < 1024) return tw[((size_t)(l * 4 + (n >> 8)) * 256 + k) * 256 + (n & 255)];
    return U[((size_t)l * 256 + k) * 768 + (n - 1024)];
}

__global__ void prep_weights_kernel(const float* __restrict__ tw,
                                    const float* __restrict__ U,
                                    const float* __restrict__ W,
                                    const float* __restrict__ tb,
                                    const float* __restrict__ gbr) {
    int t = blockIdx.x * blockDim.x + threadIdx.x;
    if (t < NBH) {
        int lane = t & 31;
        int t2 = t >> 5;
        int j2 = t2 % J2H;
        int t3 = t2 / J2H;
        int kk = t3 & 15;
        int l  = t3 >> 4;
        int g = lane >> 2, tt = lane & 3;
        int k0 = kk * 16 + tt * 2;
        uint4 o;
        {
            int n = (j2 * 2 + 0) * 8 + g;
            o.x = packh2(bvalH(tw, U, l, k0, n),     bvalH(tw, U, l, k0 + 1, n));
            o.y = packh2(bvalH(tw, U, l, k0 + 8, n), bvalH(tw, U, l, k0 + 9, n));
        }
        {
            int n = (j2 * 2 + 1) * 8 + g;
            o.z = packh2(bvalH(tw, U, l, k0, n),     bvalH(tw, U, l, k0 + 1, n));
            o.w = packh2(bvalH(tw, U, l, k0 + 8, n), bvalH(tw, U, l, k0 + 9, n));
        }
        d_BH[t] = o;
    } else if (t < NBH + NBM) {
        int tb2 = t - NBH;
        int lane = tb2 & 31;
        int t2 = tb2 >> 5;
        int j2 = t2 % J2M;
        int t3 = t2 / J2M;
        int kk = t3 & 15;
        int l  = t3 >> 4;
        int g = lane >> 2, tt = lane & 3;
        int k0 = kk * 16 + tt * 2;
        const float* Wl = W + (size_t)l * 256 * 768;
        uint4 o;
        {
            int n = (j2 * 2 + 0) * 8 + g;
            o.x = packh2(Wl[(size_t)k0 * 768 + n],       Wl[(size_t)(k0 + 1) * 768 + n]);
            o.y = packh2(Wl[(size_t)(k0 + 8) * 768 + n], Wl[(size_t)(k0 + 9) * 768 + n]);
        }
        {
            int n = (j2 * 2 + 1) * 8 + g;
            o.z = packh2(Wl[(size_t)k0 * 768 + n],       Wl[(size_t)(k0 + 1) * 768 + n]);
            o.w = packh2(Wl[(size_t)(k0 + 8) * 768 + n], Wl[(size_t)(k0 + 9) * 768 + n]);
        }
        d_BM[tb2] = o;
    } else if (t < NPREP) {
        int tb3 = t - NBH - NBM;
        int l = tb3 / 1792, n = tb3 % 1792;
        d_biasH[tb3] = (n < 1024) ? tb[l * 1024 + n] : gbr[l * 768 + (n - 1024)];
    }
}

__global__ void prep_pe_kernel() {
    int idx = blockIdx.x * blockDim.x + threadIdx.x;
    if (idx >= 513 * 256) return;
    int p = idx >> 8, i = idx & 255;
    float v = 0.0f;
    if (p > 0) {
        float div = powf(10000.0f, (2.0f * (float)i) / 256.0f);
        float ang = (float)(p - 1) / div;
        v = (i & 1) ? cosf(ang) : sinf(ang);
    }
    d_pe[idx] = v;
}

// ===================== init: h = embed + pe, also fragment layout ===========
__global__ void init_h_kernel(const int* __restrict__ nodes,
                              const float* __restrict__ embed) {
    int idx = blockIdx.x * blockDim.x + threadIdx.x;
    if (idx >= NN * 64) return;
    int n = idx >> 6;
    int c = (idx & 63) * 4;
    int tok = nodes[n];
    int pos = nodes[NN + n];
    int p = pos < 512 ? pos : 512;
    float4 e = *(const float4*)(embed + (size_t)tok * 256 + c);
    float4 pe = *(const float4*)(d_pe + (size_t)p * 256 + c);
    float4 o = make_float4(e.x + pe.x, e.y + pe.y, e.z + pe.z, e.w + pe.w);
    *(float4*)&d_h[(size_t)n * 256 + c] = o;
    store_frag(d_hp, n, c, o.x, o.y, o.z, o.w);
}

// ===================== fp16 mma GEMM: smem B, warp tile 16x128 ==============
__device__ __forceinline__ void mma16816(float* d, uint32_t a0, uint32_t a1,
                                         uint32_t a2, uint32_t a3,
                                         uint32_t b0, uint32_t b1) {
    asm volatile(
        "mma.sync.aligned.m16n8k16.row.col.f32.f16.f16.f32 "
        "{%0,%1,%2,%3}, {%4,%5,%6,%7}, {%8,%9}, {%0,%1,%2,%3};"
        : "+f"(d[0]), "+f"(d[1]), "+f"(d[2]), "+f"(d[3])
        : "r"(a0), "r"(a1), "r"(a2), "r"(a3), "r"(b0), "r"(b1));
}

// 256 threads = 8 warps; each warp owns ONE m16 tile and all 128 columns.
// CTA tile 128x128. B tile (64KB) in smem; A reg-double-buffered, no
// cross-warp A duplication (1 LDG.128 per warp per k-chunk).
__global__ __launch_bounds__(256, 2)
void gemm_h16(const uint4* __restrict__ Ap, const uint4* __restrict__ Bp,
              const float* __restrict__ bias,
              __half* __restrict__ C1, int ldC1, int split,
              __half* __restrict__ C2, int ldC2, int J2tot) {
    extern __shared__ uint4 sB[];   // [16][8][32]
    const int tid  = threadIdx.x;
    const int lane = tid & 31;
    const int wid  = tid >> 5;       // 0..7 -> m16 tile within CTA
    const int mBase = blockIdx.x * 128;
    const int colBase = blockIdx.y * 128;
    const int i0 = blockIdx.x * 8 + wid;
    const int j2cta = blockIdx.y * 8;

    const uint32_t sBu = smem_u32(sB);
#pragma unroll
    for (int i = 0; i < 16; i++) {
        int s_idx = tid + i * 256;
        int kk = s_idx >> 8;
        int rem = s_idx & 255;
        const uint4* src = Bp + (((size_t)(kk * J2tot + j2cta)) << 5) + rem;
        asm volatile("cp.async.cg.shared.global [%0], [%1], 16;"
                     :: "r"(sBu + s_idx * 16), "l"(src));
    }
    asm volatile("cp.async.commit_group;" ::: "memory");

    uint4 av = Ap[((size_t)(i0 * 16) * 32) + lane];

    float acc[16][4];
#pragma unroll
    for (int j = 0; j < 16; j++)
#pragma unroll
        for (int r = 0; r < 4; r++) acc[j][r] = 0.f;

    asm volatile("cp.async.wait_group 0;" ::: "memory");
    __syncthreads();

#pragma unroll
    for (int kk = 0; kk < 16; kk++) {
        uint4 av2;
        if (kk < 15)
            av2 = Ap[((size_t)(i0 * 16 + kk + 1) * 32) + lane];
        const uint4* sBk = sB + kk * 256;
        // first 4 j2-pairs
        {
            uint4 bq[4];
#pragma unroll
            for (int q = 0; q < 4; q++) bq[q] = sBk[q * 32 + lane];
#pragma unroll
            for (int q = 0; q < 4; q++) {
                mma16816(acc[q * 2 + 0], av.x, av.y, av.z, av.w, bq[q].x, bq[q].y);
                mma16816(acc[q * 2 + 1], av.x, av.y, av.z, av.w, bq[q].z, bq[q].w);
            }
        }
        // second 4 j2-pairs
        {
            uint4 bq[4];
#pragma unroll
            for (int q = 0; q < 4; q++) bq[q] = sBk[(4 + q) * 32 + lane];
#pragma unroll
            for (int q = 0; q < 4; q++) {
                mma16816(acc[8 + q * 2 + 0], av.x, av.y, av.z, av.w, bq[q].x, bq[q].y);
                mma16816(acc[8 + q * 2 + 1], av.x, av.y, av.z, av.w, bq[q].z, bq[q].w);
            }
        }
        if (kk < 15) av = av2;
    }

    {
        int row = mBase + wid * 16 + (lane >> 2);
#pragma unroll
        for (int j = 0; j < 16; j++) {
            int col = colBase + j * 8 + (lane & 3) * 2;
            float bx = bias[col], by = bias[col + 1];
            float a0 = acc[j][0] + bx, a1 = acc[j][1] + by;
            float a2 = acc[j][2] + bx, a3 = acc[j][3] + by;
            __half* Cout;
            int ld, cc;
            if (col < split) { Cout = C1; ld = ldC1; cc = col; }
            else             { Cout = C2; ld = ldC2; cc = col - split; }
            *(__half2*)(Cout + (size_t)row * ld + cc) = __floats2half2_rn(a0, a1);
            *(__half2*)(Cout + (size_t)(row + 8) * ld + cc) = __floats2half2_rn(a2, a3);
        }
    }
}

#define GEMM_SMEM 65536

// ===================== zero / scatter / permute / gru =======================
__global__ void zero4_kernel(uint4* __restrict__ p, int n) {
    int i = blockIdx.x * blockDim.x + threadIdx.x;
    if (i < n) p[i] = make_uint4(0u, 0u, 0u, 0u);
}

// vectorized fp16 RED scatter into row-major msgs: 1 op/lane, 32 ops/edge
__global__ void scatter_kernel(const int* __restrict__ edges,
                               __half* __restrict__ msgs) {
    int idx = blockIdx.x * blockDim.x + threadIdx.x;
    int e = idx >> 5;
    if (e >= NE) return;
    int lane = idx & 31;
    int et  = edges[e * 3 + 0];
    int src = edges[e * 3 + 1];
    int tgt = edges[e * 3 + 2];
    const uint4 v = *(const uint4*)&d_trans[((size_t)src * 4 + et) * HH + lane * 8];
    __half* dst = msgs + (size_t)tgt * HH + lane * 8;
    asm volatile("red.global.add.noftz.v4.f16x2 [%0], {%1,%2,%3,%4};"
                 :: "l"(dst), "r"(v.x), "r"(v.y), "r"(v.z), "r"(v.w)
                 : "memory");
}

// pure word-shuffle permute: row-major fp16 -> mma fragment layout
__global__ void permute_h_kernel(const __half* __restrict__ msgs) {
    int t = blockIdx.x * blockDim.x + threadIdx.x;
    if (t >= MT16 * 512) return;
    int lane = t & 31;
    int kk = (t >> 5) & 15;
    int i  = t >> 9;
    int r = lane >> 2, c2 = (lane & 3) * 2;
    int row0 = i * 16 + r, row1 = row0 + 8;
    int col0 = kk * 16 + c2;
    uint4 o = make_uint4(0u, 0u, 0u, 0u);
    if (row0 < NN) {
        o.x = *(const uint32_t*)&msgs[(size_t)row0 * 256 + col0];
        o.z = *(const uint32_t*)&msgs[(size_t)row0 * 256 + col0 + 8];
    }
    if (row1 < NN) {
        o.y = *(const uint32_t*)&msgs[(size_t)row1 * 256 + col0];
        o.w = *(const uint32_t*)&msgs[(size_t)row1 * 256 + col0 + 8];
    }
    d_msgsp[t] = o;
}

__device__ __forceinline__ float sigm(float x) { return 1.0f / (1.0f + expf(-x)); }

__global__ void gru_kernel(int write_hp) {
    int idx = blockIdx.x * blockDim.x + threadIdx.x;
    if (idx >= NN * 64) return;
    int n = idx >> 6;
    int c = (idx & 63) * 4;
    const __half2* g1 = (const __half2*)&d_g1h[(size_t)n * 768];
    const __half2* g2 = (const __half2*)&d_g2h[(size_t)n * 768];
    int c2 = c >> 1;
    float2 xz0 = __half22float2(g1[c2]),       xz1 = __half22float2(g1[c2 + 1]);
    float2 xr0 = __half22float2(g1[128 + c2]), xr1 = __half22float2(g1[128 + c2 + 1]);
    float2 xh0 = __half22float2(g1[256 + c2]), xh1 = __half22float2(g1[256 + c2 + 1]);
    float2 hz0 = __half22float2(g2[c2]),       hz1 = __half22float2(g2[c2 + 1]);
    float2 hr0 = __half22float2(g2[128 + c2]), hr1 = __half22float2(g2[128 + c2 + 1]);
    float2 hh0 = __half22float2(g2[256 + c2]), hh1 = __half22float2(g2[256 + c2 + 1]);
    float4 ho = *(float4*)&d_h[(size_t)n * 256 + c];
    float xzv[4] = {xz0.x, xz0.y, xz1.x, xz1.y};
    float xrv[4] = {xr0.x, xr0.y, xr1.x, xr1.y};
    float xhv[4] = {xh0.x, xh0.y, xh1.x, xh1.y};
    float hzv[4] = {hz0.x, hz0.y, hz1.x, hz1.y};
    float hrv[4] = {hr0.x, hr0.y, hr1.x, hr1.y};
    float hhv[4] = {hh0.x, hh0.y, hh1.x, hh1.y};
    float hov[4] = {ho.x, ho.y, ho.z, ho.w};
    float o[4];
#pragma unroll
    for (int q = 0; q < 4; q++) {
        float z = sigm(xzv[q] + hzv[q]);
        float r = sigm(xrv[q] + hrv[q]);
        float cand = tanhf(xhv[q] + r * hhv[q]);
        o[q] = z * hov[q] + (1.0f - z) * cand;
    }
    *(float4*)&d_h[(size_t)n * 256 + c] = make_float4(o[0], o[1], o[2], o[3]);
    if (write_hp) store_frag(d_hp, n, c, o[0], o[1], o[2], o[3]);
}

// ===================== readout ==============================================
__global__ void head_kernel(const float* __restrict__ gateW,
                            const float* __restrict__ gateb,
                            const float* __restrict__ outW,
                            const float* __restrict__ outb) {
    int gidx = blockIdx.x * blockDim.x + threadIdx.x;
    int warp = gidx >> 5;
    int lane = gidx & 31;
    if (warp >= NN) return;
    float g = 0.f, o0 = 0.f, o1 = 0.f;
    for (int c = lane; c < HH; c += 32) {
        float hv = d_h[(size_t)warp * HH + c];
        g  += hv * gateW[c];
        o0 += hv * outW[c * 2 + 0];
        o1 += hv * outW[c * 2 + 1];
    }
#pragma unroll
    for (int off = 16; off; off >>= 1) {
        g  += __shfl_down_sync(0xffffffffu, g,  off);
        o0 += __shfl_down_sync(0xffffffffu, o0, off);
        o1 += __shfl_down_sync(0xffffffffu, o1, off);
    }
    if (lane == 0) {
        d_gate[warp] = g + gateb[0];
        d_out2[warp * 2 + 0] = o0 + outb[0];
        d_out2[warp * 2 + 1] = o1 + outb[1];
    }
}

__global__ void max1_kernel() {
    __shared__ float s[256];
    float m = -INFINITY;
    for (int i = blockIdx.x * 256 + threadIdx.x; i < NN; i += gridDim.x * 256)
        m = fmaxf(m, d_gate[i]);
    s[threadIdx.x] = m;
    __syncthreads();
    for (int o = 128; o; o >>= 1) {
        if (threadIdx.x < o) s[threadIdx.x] = fmaxf(s[threadIdx.x], s[threadIdx.x + o]);
        __syncthreads();
    }
    if (threadIdx.x == 0) d_partial[blockIdx.x] = s[0];
}

__global__ void max2_kernel(int nb) {
    __shared__ float s[256];
    float m = (threadIdx.x < nb) ? d_partial[threadIdx.x] : -INFINITY;
    s[threadIdx.x] = m;
    __syncthreads();
    for (int o = 128; o; o >>= 1) {
        if (threadIdx.x < o) s[threadIdx.x] = fmaxf(s[threadIdx.x], s[threadIdx.x + o]);
        __syncthreads();
    }
    if (threadIdx.x == 0) d_gmax = s[0];
}

__global__ void cum_kernel(const int* __restrict__ gs) {
    if (threadIdx.x == 0 && blockIdx.x == 0) {
        int c = 0;
        d_cum[0] = 0;
        for (int i = 0; i < GG; i++) { c += gs[i]; d_cum[i + 1] = c; }
    }
}

__global__ void zero_sp_kernel() {
    int i = threadIdx.x;
    if (i < GG) d_S[i] = 0.f;
    if (i < GG * 2) d_P[i] = 0.f;
}

__global__ void accum_kernel() {
    int n = blockIdx.x * blockDim.x + threadIdx.x;
    if (n >= NN) return;
    int lo = 0, hi = GG;
    while (hi - lo > 1) {
        int mid = (lo + hi) >> 1;
        if (d_cum[mid] <= n) lo = mid; else hi = mid;
    }
    int seg = lo;
    float e = expf(d_gate[n] - d_gmax);
    atomicAdd(&d_S[seg], e);
    atomicAdd(&d_P[seg * 2 + 0], e * d_out2[n * 2 + 0]);
    atomicAdd(&d_P[seg * 2 + 1], e * d_out2[n * 2 + 1]);
}

__global__ void final_kernel(float* __restrict__ out) {
    int i = threadIdx.x;
    if (i < GG * 2) out[i] = d_P[i] / (d_S[i >> 1] + 1e-16f);
}

// ===================== host orchestration ===================================
extern "C" void kernel_launch(void* const* d_in, const int* in_sizes, int n_in,
                              void* d_out, int out_size) {
    const int*   nodes       = (const int*)d_in[0];
    const int*   graph_sizes = (const int*)d_in[1];
    const int*   edges       = (const int*)d_in[2];
    const float* embed       = (const float*)d_in[3];
    const float* tw          = (const float*)d_in[4];
    const float* tb          = (const float*)d_in[5];
    const float* gruW        = (const float*)d_in[6];
    const float* gruU        = (const float*)d_in[7];
    const float* gbi         = (const float*)d_in[8];
    const float* gbr         = (const float*)d_in[9];
    const float* gateW       = (const float*)d_in[10];
    const float* gateb       = (const float*)d_in[11];
    const float* outW        = (const float*)d_in[12];
    const float* outb        = (const float*)d_in[13];
    float* out = (float*)d_out;

    float *p_biasH;
    __half *p_trans, *p_msgsh, *p_g1h, *p_g2h;
    uint4 *p_hp, *p_msgsp, *p_BH, *p_BM;
    cudaGetSymbolAddress((void**)&p_trans, d_trans);
    cudaGetSymbolAddress((void**)&p_msgsh, d_msgsh);
    cudaGetSymbolAddress((void**)&p_g1h, d_g1h);
    cudaGetSymbolAddress((void**)&p_g2h, d_g2h);
    cudaGetSymbolAddress((void**)&p_biasH, d_biasH);
    cudaGetSymbolAddress((void**)&p_hp, d_hp);
    cudaGetSymbolAddress((void**)&p_msgsp, d_msgsp);
    cudaGetSymbolAddress((void**)&p_BH, d_BH);
    cudaGetSymbolAddress((void**)&p_BM, d_BM);

    cudaFuncSetAttribute(gemm_h16, cudaFuncAttributeMaxDynamicSharedMemorySize,
                         GEMM_SMEM);

    const int layers[4] = {0, 0, 0, 1};
    const int gridM = NN_PAD / 128;               // 782
    const size_t msgsStep = (size_t)NN * HH;
    const int allZeroN = (int)(4 * msgsStep * 2 / 16);
    const int permN = MT16 * 512;

    // prep phase: weights, pe, bulk-zero all 4 msgs buffers, init h
    prep_weights_kernel<<<(NPREP + 255) / 256, 256>>>(tw, gruU, gruW, tb, gbr);
    prep_pe_kernel<<<(513 * 256 + 255) / 256, 256>>>();
    zero4_kernel<<<(allZeroN + 255) / 256, 256>>>((uint4*)p_msgsh, allZeroN);
    init_h_kernel<<<(NN * 64 + 255) / 256, 256>>>(nodes, embed);

    for (int s = 0; s < 4; s++) {
        int l = layers[s];
        __half* msgs = p_msgsh + (size_t)s * msgsStep;
        // fused: h @ [typeW(1024 -> trans fp16) | gruU(768 -> g2h fp16)]
        gemm_h16<<<dim3(gridM, 14), 256, GEMM_SMEM>>>(
            p_hp, p_BH + (size_t)l * 16 * J2H * 32, p_biasH + l * 1792,
            p_trans, 1024, 1024, p_g2h, 768, J2H);
        scatter_kernel<<<(size_t)NE * 32 / 256, 256>>>(edges, msgs);
        permute_h_kernel<<<(permN + 255) / 256, 256>>>(msgs);
        gemm_h16<<<dim3(gridM, 6), 256, GEMM_SMEM>>>(
            p_msgsp, p_BM + (size_t)l * 16 * J2M * 32, gbi + l * 768,
            p_g1h, 768, 1 << 28, p_g1h, 768, J2M);
        gru_kernel<<<(NN * 64 + 255) / 256, 256>>>(s < 3 ? 1 : 0);
    }

    head_kernel<<<(NN * 32 + 255) / 256, 256>>>(gateW, gateb, outW, outb);
    max1_kernel<<<256, 256>>>();
    max2_kernel<<<1, 256>>>(256);
    cum_kernel<<<1, 1>>>(graph_sizes);
    zero_sp_kernel<<<1, 256>>>();
    accum_kernel<<<(NN + 255) / 256, 256>>>();
    final_kernel<<<1, 256>>>(out);
}

// round 16
// speedup vs baseline: 1.0407x; 1.0407x over previous
#include <cuda_runtime.h>
#include <cuda_fp16.h>
#include <cstdint>
#include <math.h>

#define NN 100000
#define NN_PAD 100096
#define MT16 (NN_PAD / 16)        // 6256 m16 tiles
#define GG 100
#define NE 1000000
#define HH 256
#define TT 4
#define J2H 112                   // 1792/16 n8-tile-pairs for fused h GEMM
#define J2M 48                    // 768/16 for msgs GEMM

// ===================== scratch (device globals) =============================
__device__ float  d_h[(size_t)NN * HH];
__device__ __half d_trans[(size_t)NN_PAD * TT * HH];  // [node][t][256] fp16
__device__ __half d_msgsh[4][(size_t)NN * HH];        // per-step fp16 msgs
__device__ __half d_g1h[(size_t)NN_PAD * 3 * HH];     // fp16 gates (msgs@W)
__device__ __half d_g2h[(size_t)NN_PAD * 3 * HH];     // fp16 gates (h@U)
__device__ uint4  d_hp[(size_t)MT16 * 512];           // permuted fp16 A (h)
__device__ uint4  d_msgsp[(size_t)MT16 * 512];        // permuted fp16 A (msgs)
__device__ uint4  d_BH[(size_t)2 * 16 * J2H * 32];    // permuted fp16 B (tw|U)
__device__ uint4  d_BM[(size_t)2 * 16 * J2M * 32];    // permuted fp16 B (W)
__device__ float  d_biasH[2 * 1792];
__device__ float  d_pe[513 * 256];
__device__ float  d_gate[NN];
__device__ float  d_out2[NN * 2];
__device__ float  d_partial[256];
__device__ float  d_gmax;
__device__ int    d_cum[GG + 1];
__device__ float  d_S[GG];
__device__ float  d_P[GG * 2];

__device__ __forceinline__ uint32_t packh2(float lo, float hi) {
    __half2 h = __floats2half2_rn(lo, hi);
    return *reinterpret_cast<uint32_t*>(&h);
}
__device__ __forceinline__ uint32_t smem_u32(const void* p) {
    uint32_t a;
    asm("{ .reg .u64 t; cvta.to.shared.u64 t, %1; cvt.u32.u64 %0, t; }"
        : "=r"(a) : "l"(p));
    return a;
}

// write 4 consecutive values (row n, cols c..c+3) into fragment layout at dst
__device__ __forceinline__ void store_frag(uint4* dst, int n, int c, float v0,
                                           float v1, float v2, float v3) {
    int i = n >> 4, r = n & 15, kk = c >> 4, cl = c & 15;
    uint32_t comp = ((cl >= 8) ? 8u : 0u) + ((r >= 8) ? 4u : 0u);
    int lane0 = (r & 7) * 4 + ((cl & 7) >> 1);
    char* base = (char*)dst + (((size_t)i * 512 + (size_t)kk * 32) * 16) + comp;
    *(__half2*)(base + (size_t)lane0 * 16)       = __floats2half2_rn(v0, v1);
    *(__half2*)(base + (size_t)(lane0 + 1) * 16) = __floats2half2_rn(v2, v3);
}

// ===================== merged weight prep (1 launch) ========================
#define NBH (2 * 16 * J2H * 32)   // 114688
#define NBM (2 * 16 * J2M * 32)   // 49152
#define NPREP (NBH + NBM + 2 * 1792)

__device__ __forceinline__ float bvalH(const float* tw, const float* U,
                                       int l, int k, int n) {
    if (n < 1024) return tw[((size_t)(l * 4 + (n >> 8)) * 256 + k) * 256 + (n & 255)];
    return U[((size_t)l * 256 + k) * 768 + (n - 1024)];
}

__global__ void prep_weights_kernel(const float* __restrict__ tw,
                                    const float* __restrict__ U,
                                    const float* __restrict__ W,
                                    const float* __restrict__ tb,
                                    const float* __restrict__ gbr) {
    int t = blockIdx.x * blockDim.x + threadIdx.x;
    if (t < NBH) {
        int lane = t & 31;
        int t2 = t >> 5;
        int j2 = t2 % J2H;
        int t3 = t2 / J2H;
        int kk = t3 & 15;
        int l  = t3 >> 4;
        int g = lane >> 2, tt = lane & 3;
        int k0 = kk * 16 + tt * 2;
        uint4 o;
        {
            int n = (j2 * 2 + 0) * 8 + g;
            o.x = packh2(bvalH(tw, U, l, k0, n),     bvalH(tw, U, l, k0 + 1, n));
            o.y = packh2(bvalH(tw, U, l, k0 + 8, n), bvalH(tw, U, l, k0 + 9, n));
        }
        {
            int n = (j2 * 2 + 1) * 8 + g;
            o.z = packh2(bvalH(tw, U, l, k0, n),     bvalH(tw, U, l, k0 + 1, n));
            o.w = packh2(bvalH(tw, U, l, k0 + 8, n), bvalH(tw, U, l, k0 + 9, n));
        }
        d_BH[t] = o;
    } else if (t < NBH + NBM) {
        int tb2 = t - NBH;
        int lane = tb2 & 31;
        int t2 = tb2 >> 5;
        int j2 = t2 % J2M;
        int t3 = t2 / J2M;
        int kk = t3 & 15;
        int l  = t3 >> 4;
        int g = lane >> 2, tt = lane & 3;
        int k0 = kk * 16 + tt * 2;
        const float* Wl = W + (size_t)l * 256 * 768;
        uint4 o;
        {
            int n = (j2 * 2 + 0) * 8 + g;
            o.x = packh2(Wl[(size_t)k0 * 768 + n],       Wl[(size_t)(k0 + 1) * 768 + n]);
            o.y = packh2(Wl[(size_t)(k0 + 8) * 768 + n], Wl[(size_t)(k0 + 9) * 768 + n]);
        }
        {
            int n = (j2 * 2 + 1) * 8 + g;
            o.z = packh2(Wl[(size_t)k0 * 768 + n],       Wl[(size_t)(k0 + 1) * 768 + n]);
            o.w = packh2(Wl[(size_t)(k0 + 8) * 768 + n], Wl[(size_t)(k0 + 9) * 768 + n]);
        }
        d_BM[tb2] = o;
    } else if (t < NPREP) {
        int tb3 = t - NBH - NBM;
        int l = tb3 / 1792, n = tb3 % 1792;
        d_biasH[tb3] = (n < 1024) ? tb[l * 1024 + n] : gbr[l * 768 + (n - 1024)];
    }
}

__global__ void prep_pe_kernel() {
    int idx = blockIdx.x * blockDim.x + threadIdx.x;
    if (idx >= 513 * 256) return;
    int p = idx >> 8, i = idx & 255;
    float v = 0.0f;
    if (p > 0) {
        float div = powf(10000.0f, (2.0f * (float)i) / 256.0f);
        float ang = (float)(p - 1) / div;
        v = (i & 1) ? cosf(ang) : sinf(ang);
    }
    d_pe[idx] = v;
}

// ===================== init: h = embed + pe, also fragment layout ===========
__global__ void init_h_kernel(const int* __restrict__ nodes,
                              const float* __restrict__ embed) {
    int idx = blockIdx.x * blockDim.x + threadIdx.x;
    if (idx >= NN * 64) return;
    int n = idx >> 6;
    int c = (idx & 63) * 4;
    int tok = nodes[n];
    int pos = nodes[NN + n];
    int p = pos < 512 ? pos : 512;
    float4 e = *(const float4*)(embed + (size_t)tok * 256 + c);
    float4 pe = *(const float4*)(d_pe + (size_t)p * 256 + c);
    float4 o = make_float4(e.x + pe.x, e.y + pe.y, e.z + pe.z, e.w + pe.w);
    *(float4*)&d_h[(size_t)n * 256 + c] = o;
    store_frag(d_hp, n, c, o.x, o.y, o.z, o.w);
}

// ===================== fp16 mma GEMM: smem B + wave-staged smem A ===========
__device__ __forceinline__ void mma16816(float* d, uint32_t a0, uint32_t a1,
                                         uint32_t a2, uint32_t a3,
                                         uint32_t b0, uint32_t b1) {
    asm volatile(
        "mma.sync.aligned.m16n8k16.row.col.f32.f16.f16.f32 "
        "{%0,%1,%2,%3}, {%4,%5,%6,%7}, {%8,%9}, {%0,%1,%2,%3};"
        : "+f"(d[0]), "+f"(d[1]), "+f"(d[2]), "+f"(d[3])
        : "r"(a0), "r"(a1), "r"(a2), "r"(a3), "r"(b0), "r"(b1));
}

// 256 threads = 4x2 warps, warp tile 32(M) x 64(N). CTA tile 128x128.
// B (64KB) staged once; A staged in 4-chunk waves via 3-deep smem ring
// (16KB/wave): 1 wait_group + 1 barrier per wave (4 total).
__global__ __launch_bounds__(256, 2)
void gemm_h16(const uint4* __restrict__ Ap, const uint4* __restrict__ Bp,
              const float* __restrict__ bias,
              __half* __restrict__ C1, int ldC1, int split,
              __half* __restrict__ C2, int ldC2, int J2tot) {
    extern __shared__ uint4 smem[];
    uint4* sB = smem;              // [16][8][32] = 4096 uint4 = 64KB
    uint4* sA = smem + 4096;       // [3][4][8][32] = 3072 uint4 = 48KB
    const int tid  = threadIdx.x;
    const int lane = tid & 31;
    const int wid  = tid >> 5;
    const int wr = wid & 3;
    const int wc = wid >> 2;
    const int mBase = blockIdx.x * 128;
    const int colBase = blockIdx.y * 128;
    const int i0cta = blockIdx.x * 8;
    const int j2cta = blockIdx.y * 8;
    const uint32_t sBu = smem_u32(sB);
    const uint32_t sAu = smem_u32(sA);
    const int atile = tid >> 5;    // staging: this thread loads tile atile

    // G1: B tile + A wave 0 (chunks 0-3)
#pragma unroll
    for (int i = 0; i < 16; i++) {
        int s_idx = tid + i * 256;
        int kk = s_idx >> 8;
        int rem = s_idx & 255;
        const uint4* src = Bp + (((size_t)(kk * J2tot + j2cta)) << 5) + rem;
        asm volatile("cp.async.cg.shared.global [%0], [%1], 16;"
                     :: "r"(sBu + s_idx * 16), "l"(src));
    }
#pragma unroll
    for (int c = 0; c < 4; c++) {
        const uint4* src = Ap + ((size_t)((i0cta + atile) * 16 + c) * 32) + lane;
        asm volatile("cp.async.cg.shared.global [%0], [%1], 16;"
                     :: "r"(sAu + (c * 256 + tid) * 16), "l"(src));
    }
    asm volatile("cp.async.commit_group;" ::: "memory");
    // G2: A wave 1 (chunks 4-7) -> ring slot 1
#pragma unroll
    for (int c = 0; c < 4; c++) {
        const uint4* src = Ap + ((size_t)((i0cta + atile) * 16 + 4 + c) * 32) + lane;
        asm volatile("cp.async.cg.shared.global [%0], [%1], 16;"
                     :: "r"(sAu + ((1024 + c * 256) + tid) * 16), "l"(src));
    }
    asm volatile("cp.async.commit_group;" ::: "memory");

    float acc[2][8][4];
#pragma unroll
    for (int mi = 0; mi < 2; mi++)
#pragma unroll
        for (int j = 0; j < 8; j++)
#pragma unroll
            for (int r = 0; r < 4; r++) acc[mi][j][r] = 0.f;

#pragma unroll
    for (int w = 0; w < 4; w++) {
        asm volatile("cp.async.wait_group 1;" ::: "memory");
        __syncthreads();
        // issue wave w+2 into ring slot (w+2)%3 (free: last read in wave w-1)
        if (w + 2 < 4) {
            int slot = (w + 2) % 3;
#pragma unroll
            for (int c = 0; c < 4; c++) {
                const uint4* src = Ap +
                    ((size_t)((i0cta + atile) * 16 + (w + 2) * 4 + c) * 32) + lane;
                asm volatile("cp.async.cg.shared.global [%0], [%1], 16;"
                             :: "r"(sAu + ((slot * 1024 + c * 256) + tid) * 16),
                                "l"(src));
            }
        }
        asm volatile("cp.async.commit_group;" ::: "memory");

        const uint4* sAw = sA + (w % 3) * 1024 + (wr * 2) * 32;
#pragma unroll
        for (int cc = 0; cc < 4; cc++) {
            int kk = w * 4 + cc;
            uint4 av[2], bq[4];
            av[0] = sAw[cc * 256 + lane];
            av[1] = sAw[cc * 256 + 32 + lane];
#pragma unroll
            for (int q = 0; q < 4; q++)
                bq[q] = sB[(kk * 8 + wc * 4 + q) * 32 + lane];
#pragma unroll
            for (int mi = 0; mi < 2; mi++) {
#pragma unroll
                for (int q = 0; q < 4; q++) {
                    mma16816(acc[mi][q * 2 + 0], av[mi].x, av[mi].y, av[mi].z,
                             av[mi].w, bq[q].x, bq[q].y);
                    mma16816(acc[mi][q * 2 + 1], av[mi].x, av[mi].y, av[mi].z,
                             av[mi].w, bq[q].z, bq[q].w);
                }
            }
        }
    }

#pragma unroll
    for (int mi = 0; mi < 2; mi++) {
        int row = mBase + wr * 32 + mi * 16 + (lane >> 2);
#pragma unroll
        for (int j = 0; j < 8; j++) {
            int col = colBase + wc * 64 + j * 8 + (lane & 3) * 2;
            float bx = bias[col], by = bias[col + 1];
            float a0 = acc[mi][j][0] + bx, a1 = acc[mi][j][1] + by;
            float a2 = acc[mi][j][2] + bx, a3 = acc[mi][j][3] + by;
            __half* Cout;
            int ld, cc;
            if (col < split) { Cout = C1; ld = ldC1; cc = col; }
            else             { Cout = C2; ld = ldC2; cc = col - split; }
            *(__half2*)(Cout + (size_t)row * ld + cc) = __floats2half2_rn(a0, a1);
            *(__half2*)(Cout + (size_t)(row + 8) * ld + cc) = __floats2half2_rn(a2, a3);
        }
    }
}

#define GEMM_SMEM (64 * 1024 + 48 * 1024)

// ===================== zero / scatter / permute / gru =======================
__global__ void zero4_kernel(uint4* __restrict__ p, int n) {
    int i = blockIdx.x * blockDim.x + threadIdx.x;
    if (i < n) p[i] = make_uint4(0u, 0u, 0u, 0u);
}

// vectorized fp16 RED scatter into row-major msgs: 1 op/lane, 32 ops/edge
__global__ void scatter_kernel(const int* __restrict__ edges,
                               __half* __restrict__ msgs) {
    int idx = blockIdx.x * blockDim.x + threadIdx.x;
    int e = idx >> 5;
    if (e >= NE) return;
    int lane = idx & 31;
    int et  = edges[e * 3 + 0];
    int src = edges[e * 3 + 1];
    int tgt = edges[e * 3 + 2];
    const uint4 v = *(const uint4*)&d_trans[((size_t)src * 4 + et) * HH + lane * 8];
    __half* dst = msgs + (size_t)tgt * HH + lane * 8;
    asm volatile("red.global.add.noftz.v4.f16x2 [%0], {%1,%2,%3,%4};"
                 :: "l"(dst), "r"(v.x), "r"(v.y), "r"(v.z), "r"(v.w)
                 : "memory");
}

// pure word-shuffle permute: row-major fp16 -> mma fragment layout
__global__ void permute_h_kernel(const __half* __restrict__ msgs) {
    int t = blockIdx.x * blockDim.x + threadIdx.x;
    if (t >= MT16 * 512) return;
    int lane = t & 31;
    int kk = (t >> 5) & 15;
    int i  = t >> 9;
    int r = lane >> 2, c2 = (lane & 3) * 2;
    int row0 = i * 16 + r, row1 = row0 + 8;
    int col0 = kk * 16 + c2;
    uint4 o = make_uint4(0u, 0u, 0u, 0u);
    if (row0 < NN) {
        o.x = *(const uint32_t*)&msgs[(size_t)row0 * 256 + col0];
        o.z = *(const uint32_t*)&msgs[(size_t)row0 * 256 + col0 + 8];
    }
    if (row1 < NN) {
        o.y = *(const uint32_t*)&msgs[(size_t)row1 * 256 + col0];
        o.w = *(const uint32_t*)&msgs[(size_t)row1 * 256 + col0 + 8];
    }
    d_msgsp[t] = o;
}

__device__ __forceinline__ float sigm(float x) { return 1.0f / (1.0f + expf(-x)); }

__global__ void gru_kernel(int write_hp) {
    int idx = blockIdx.x * blockDim.x + threadIdx.x;
    if (idx >= NN * 64) return;
    int n = idx >> 6;
    int c = (idx & 63) * 4;
    const __half2* g1 = (const __half2*)&d_g1h[(size_t)n * 768];
    const __half2* g2 = (const __half2*)&d_g2h[(size_t)n * 768];
    int c2 = c >> 1;
    float2 xz0 = __half22float2(g1[c2]),       xz1 = __half22float2(g1[c2 + 1]);
    float2 xr0 = __half22float2(g1[128 + c2]), xr1 = __half22float2(g1[128 + c2 + 1]);
    float2 xh0 = __half22float2(g1[256 + c2]), xh1 = __half22float2(g1[256 + c2 + 1]);
    float2 hz0 = __half22float2(g2[c2]),       hz1 = __half22float2(g2[c2 + 1]);
    float2 hr0 = __half22float2(g2[128 + c2]), hr1 = __half22float2(g2[128 + c2 + 1]);
    float2 hh0 = __half22float2(g2[256 + c2]), hh1 = __half22float2(g2[256 + c2 + 1]);
    float4 ho = *(float4*)&d_h[(size_t)n * 256 + c];
    float xzv[4] = {xz0.x, xz0.y, xz1.x, xz1.y};
    float xrv[4] = {xr0.x, xr0.y, xr1.x, xr1.y};
    float xhv[4] = {xh0.x, xh0.y, xh1.x, xh1.y};
    float hzv[4] = {hz0.x, hz0.y, hz1.x, hz1.y};
    float hrv[4] = {hr0.x, hr0.y, hr1.x, hr1.y};
    float hhv[4] = {hh0.x, hh0.y, hh1.x, hh1.y};
    float hov[4] = {ho.x, ho.y, ho.z, ho.w};
    float o[4];
#pragma unroll
    for (int q = 0; q < 4; q++) {
        float z = sigm(xzv[q] + hzv[q]);
        float r = sigm(xrv[q] + hrv[q]);
        float cand = tanhf(xhv[q] + r * hhv[q]);
        o[q] = z * hov[q] + (1.0f - z) * cand;
    }
    *(float4*)&d_h[(size_t)n * 256 + c] = make_float4(o[0], o[1], o[2], o[3]);
    if (write_hp) store_frag(d_hp, n, c, o[0], o[1], o[2], o[3]);
}

// ===================== readout ==============================================
__global__ void head_kernel(const float* __restrict__ gateW,
                            const float* __restrict__ gateb,
                            const float* __restrict__ outW,
                            const float* __restrict__ outb) {
    int gidx = blockIdx.x * blockDim.x + threadIdx.x;
    int warp = gidx >> 5;
    int lane = gidx & 31;
    if (warp >= NN) return;
    float g = 0.f, o0 = 0.f, o1 = 0.f;
    for (int c = lane; c < HH; c += 32) {
        float hv = d_h[(size_t)warp * HH + c];
        g  += hv * gateW[c];
        o0 += hv * outW[c * 2 + 0];
        o1 += hv * outW[c * 2 + 1];
    }
#pragma unroll
    for (int off = 16; off; off >>= 1) {
        g  += __shfl_down_sync(0xffffffffu, g,  off);
        o0 += __shfl_down_sync(0xffffffffu, o0, off);
        o1 += __shfl_down_sync(0xffffffffu, o1, off);
    }
    if (lane == 0) {
        d_gate[warp] = g + gateb[0];
        d_out2[warp * 2 + 0] = o0 + outb[0];
        d_out2[warp * 2 + 1] = o1 + outb[1];
    }
}

__global__ void max1_kernel() {
    __shared__ float s[256];
    float m = -INFINITY;
    for (int i = blockIdx.x * 256 + threadIdx.x; i < NN; i += gridDim.x * 256)
        m = fmaxf(m, d_gate[i]);
    s[threadIdx.x] = m;
    __syncthreads();
    for (int o = 128; o; o >>= 1) {
        if (threadIdx.x < o) s[threadIdx.x] = fmaxf(s[threadIdx.x], s[threadIdx.x + o]);
        __syncthreads();
    }
    if (threadIdx.x == 0) d_partial[blockIdx.x] = s[0];
}

__global__ void max2_kernel(int nb) {
    __shared__ float s[256];
    float m = (threadIdx.x < nb) ? d_partial[threadIdx.x] : -INFINITY;
    s[threadIdx.x] = m;
    __syncthreads();
    for (int o = 128; o; o >>= 1) {
        if (threadIdx.x < o) s[threadIdx.x] = fmaxf(s[threadIdx.x], s[threadIdx.x + o]);
        __syncthreads();
    }
    if (threadIdx.x == 0) d_gmax = s[0];
}

__global__ void cum_kernel(const int* __restrict__ gs) {
    if (threadIdx.x == 0 && blockIdx.x == 0) {
        int c = 0;
        d_cum[0] = 0;
        for (int i = 0; i < GG; i++) { c += gs[i]; d_cum[i + 1] = c; }
    }
}

__global__ void zero_sp_kernel() {
    int i = threadIdx.x;
    if (i < GG) d_S[i] = 0.f;
    if (i < GG * 2) d_P[i] = 0.f;
}

__global__ void accum_kernel() {
    int n = blockIdx.x * blockDim.x + threadIdx.x;
    if (n >= NN) return;
    int lo = 0, hi = GG;
    while (hi - lo > 1) {
        int mid = (lo + hi) >> 1;
        if (d_cum[mid] <= n) lo = mid; else hi = mid;
    }
    int seg = lo;
    float e = expf(d_gate[n] - d_gmax);
    atomicAdd(&d_S[seg], e);
    atomicAdd(&d_P[seg * 2 + 0], e * d_out2[n * 2 + 0]);
    atomicAdd(&d_P[seg * 2 + 1], e * d_out2[n * 2 + 1]);
}

__global__ void final_kernel(float* __restrict__ out) {
    int i = threadIdx.x;
    if (i < GG * 2) out[i] = d_P[i] / (d_S[i >> 1] + 1e-16f);
}

// ===================== host orchestration ===================================
extern "C" void kernel_launch(void* const* d_in, const int* in_sizes, int n_in,
                              void* d_out, int out_size) {
    const int*   nodes       = (const int*)d_in[0];
    const int*   graph_sizes = (const int*)d_in[1];
    const int*   edges       = (const int*)d_in[2];
    const float* embed       = (const float*)d_in[3];
    const float* tw          = (const float*)d_in[4];
    const float* tb          = (const float*)d_in[5];
    const float* gruW        = (const float*)d_in[6];
    const float* gruU        = (const float*)d_in[7];
    const float* gbi         = (const float*)d_in[8];
    const float* gbr         = (const float*)d_in[9];
    const float* gateW       = (const float*)d_in[10];
    const float* gateb       = (const float*)d_in[11];
    const float* outW        = (const float*)d_in[12];
    const float* outb        = (const float*)d_in[13];
    float* out = (float*)d_out;

    float *p_biasH;
    __half *p_trans, *p_msgsh, *p_g1h, *p_g2h;
    uint4 *p_hp, *p_msgsp, *p_BH, *p_BM;
    cudaGetSymbolAddress((void**)&p_trans, d_trans);
    cudaGetSymbolAddress((void**)&p_msgsh, d_msgsh);
    cudaGetSymbolAddress((void**)&p_g1h, d_g1h);
    cudaGetSymbolAddress((void**)&p_g2h, d_g2h);
    cudaGetSymbolAddress((void**)&p_biasH, d_biasH);
    cudaGetSymbolAddress((void**)&p_hp, d_hp);
    cudaGetSymbolAddress((void**)&p_msgsp, d_msgsp);
    cudaGetSymbolAddress((void**)&p_BH, d_BH);
    cudaGetSymbolAddress((void**)&p_BM, d_BM);

    cudaFuncSetAttribute(gemm_h16, cudaFuncAttributeMaxDynamicSharedMemorySize,
                         GEMM_SMEM);

    const int layers[4] = {0, 0, 0, 1};
    const int gridM = NN_PAD / 128;               // 782
    const size_t msgsStep = (size_t)NN * HH;
    const int allZeroN = (int)(4 * msgsStep * 2 / 16);
    const int permN = MT16 * 512;

    // prep phase: weights, pe, bulk-zero all 4 msgs buffers, init h
    prep_weights_kernel<<<(NPREP + 255) / 256, 256>>>(tw, gruU, gruW, tb, gbr);
    prep_pe_kernel<<<(513 * 256 + 255) / 256, 256>>>();
    zero4_kernel<<<(allZeroN + 255) / 256, 256>>>((uint4*)p_msgsh, allZeroN);
    init_h_kernel<<<(NN * 64 + 255) / 256, 256>>>(nodes, embed);

    for (int s = 0; s < 4; s++) {
        int l = layers[s];
        __half* msgs = p_msgsh + (size_t)s * msgsStep;
        // fused: h @ [typeW(1024 -> trans fp16) | gruU(768 -> g2h fp16)]
        gemm_h16<<<dim3(gridM, 14), 256, GEMM_SMEM>>>(
            p_hp, p_BH + (size_t)l * 16 * J2H * 32, p_biasH + l * 1792,
            p_trans, 1024, 1024, p_g2h, 768, J2H);
        scatter_kernel<<<(size_t)NE * 32 / 256, 256>>>(edges, msgs);
        permute_h_kernel<<<(permN + 255) / 256, 256>>>(msgs);
        gemm_h16<<<dim3(gridM, 6), 256, GEMM_SMEM>>>(
            p_msgsp, p_BM + (size_t)l * 16 * J2M * 32, gbi + l * 768,
            p_g1h, 768, 1 << 28, p_g1h, 768, J2M);
        gru_kernel<<<(NN * 64 + 255) / 256, 256>>>(s < 3 ? 1 : 0);
    }

    head_kernel<<<(NN * 32 + 255) / 256, 256>>>(gateW, gateb, outW, outb);
    max1_kernel<<<256, 256>>>();
    max2_kernel<<<1, 256>>>(256);
    cum_kernel<<<1, 1>>>(graph_sizes);
    zero_sp_kernel<<<1, 256>>>();
    accum_kernel<<<(NN + 255) / 256, 256>>>();
    final_kernel<<<1, 256>>>(out);
}

// round 17
// speedup vs baseline: 1.1520x; 1.1069x over previous
#include <cuda_runtime.h>
#include <cuda_fp16.h>
#include <cstdint>
#include <math.h>

#define NN 100000
#define NN_PAD 100096
#define MT16 (NN_PAD / 16)        // 6256 m16 tiles
#define GG 100
#define NE 1000000
#define HH 256
#define TT 4
#define J2H 112                   // 1792/16 n8-tile-pairs for fused h GEMM
#define J2M 48                    // 768/16 for msgs GEMM

// ===================== scratch (device globals) =============================
__device__ float  d_h[(size_t)NN * HH];
__device__ __half d_trans[(size_t)NN_PAD * TT * HH];  // [node][t][256] fp16
__device__ __half d_msgsh[(size_t)NN * HH];           // row-major fp16 msgs
__device__ __half d_g1h[(size_t)NN_PAD * 3 * HH];     // fp16 gates (msgs@W)
__device__ __half d_g2h[(size_t)NN_PAD * 3 * HH];     // fp16 gates (h@U)
__device__ uint4  d_hp[(size_t)MT16 * 512];           // permuted fp16 A (h)
__device__ uint4  d_msgsp[(size_t)MT16 * 512];        // permuted fp16 A (msgs)
__device__ uint4  d_BH[(size_t)2 * 16 * J2H * 32];    // permuted fp16 B (tw|U)
__device__ uint4  d_BM[(size_t)2 * 16 * J2M * 32];    // permuted fp16 B (W)
__device__ float  d_biasH[2 * 1792];
__device__ float  d_pe[513 * 256];
__device__ float  d_gate[NN];
__device__ float  d_out2[NN * 2];
__device__ float  d_partial[256];
__device__ float  d_gmax;
__device__ int    d_cum[GG + 1];
__device__ float  d_S[GG];
__device__ float  d_P[GG * 2];

__device__ __forceinline__ uint32_t packh2(float lo, float hi) {
    __half2 h = __floats2half2_rn(lo, hi);
    return *reinterpret_cast<uint32_t*>(&h);
}
__device__ __forceinline__ uint32_t smem_u32(const void* p) {
    uint32_t a;
    asm("{ .reg .u64 t; cvta.to.shared.u64 t, %1; cvt.u32.u64 %0, t; }"
        : "=r"(a) : "l"(p));
    return a;
}

// write 4 consecutive values (row n, cols c..c+3) into fragment layout at dst
__device__ __forceinline__ void store_frag(uint4* dst, int n, int c, float v0,
                                           float v1, float v2, float v3) {
    int i = n >> 4, r = n & 15, kk = c >> 4, cl = c & 15;
    uint32_t comp = ((cl >= 8) ? 8u : 0u) + ((r >= 8) ? 4u : 0u);
    int lane0 = (r & 7) * 4 + ((cl & 7) >> 1);
    char* base = (char*)dst + (((size_t)i * 512 + (size_t)kk * 32) * 16) + comp;
    *(__half2*)(base + (size_t)lane0 * 16)       = __floats2half2_rn(v0, v1);
    *(__half2*)(base + (size_t)(lane0 + 1) * 16) = __floats2half2_rn(v2, v3);
}

// ===================== merged weight prep (1 launch) ========================
#define NBH (2 * 16 * J2H * 32)   // 114688
#define NBM (2 * 16 * J2M * 32)   // 49152
#define NPREP (NBH + NBM + 2 * 1792)

__device__ __forceinline__ float bvalH(const float* tw, const float* U,
                                       int l, int k, int n) {
    if (n < 1024) return tw[((size_t)(l * 4 + (n >> 8)) * 256 + k) * 256 + (n & 255)];
    return U[((size_t)l * 256 + k) * 768 + (n - 1024)];
}

__global__ void prep_weights_kernel(const float* __restrict__ tw,
                                    const float* __restrict__ U,
                                    const float* __restrict__ W,
                                    const float* __restrict__ tb,
                                    const float* __restrict__ gbr) {
    int t = blockIdx.x * blockDim.x + threadIdx.x;
    if (t < NBH) {
        int lane = t & 31;
        int t2 = t >> 5;
        int j2 = t2 % J2H;
        int t3 = t2 / J2H;
        int kk = t3 & 15;
        int l  = t3 >> 4;
        int g = lane >> 2, tt = lane & 3;
        int k0 = kk * 16 + tt * 2;
        uint4 o;
        {
            int n = (j2 * 2 + 0) * 8 + g;
            o.x = packh2(bvalH(tw, U, l, k0, n),     bvalH(tw, U, l, k0 + 1, n));
            o.y = packh2(bvalH(tw, U, l, k0 + 8, n), bvalH(tw, U, l, k0 + 9, n));
        }
        {
            int n = (j2 * 2 + 1) * 8 + g;
            o.z = packh2(bvalH(tw, U, l, k0, n),     bvalH(tw, U, l, k0 + 1, n));
            o.w = packh2(bvalH(tw, U, l, k0 + 8, n), bvalH(tw, U, l, k0 + 9, n));
        }
        d_BH[t] = o;
    } else if (t < NBH + NBM) {
        int tb2 = t - NBH;
        int lane = tb2 & 31;
        int t2 = tb2 >> 5;
        int j2 = t2 % J2M;
        int t3 = t2 / J2M;
        int kk = t3 & 15;
        int l  = t3 >> 4;
        int g = lane >> 2, tt = lane & 3;
        int k0 = kk * 16 + tt * 2;
        const float* Wl = W + (size_t)l * 256 * 768;
        uint4 o;
        {
            int n = (j2 * 2 + 0) * 8 + g;
            o.x = packh2(Wl[(size_t)k0 * 768 + n],       Wl[(size_t)(k0 + 1) * 768 + n]);
            o.y = packh2(Wl[(size_t)(k0 + 8) * 768 + n], Wl[(size_t)(k0 + 9) * 768 + n]);
        }
        {
            int n = (j2 * 2 + 1) * 8 + g;
            o.z = packh2(Wl[(size_t)k0 * 768 + n],       Wl[(size_t)(k0 + 1) * 768 + n]);
            o.w = packh2(Wl[(size_t)(k0 + 8) * 768 + n], Wl[(size_t)(k0 + 9) * 768 + n]);
        }
        d_BM[tb2] = o;
    } else if (t < NPREP) {
        int tb3 = t - NBH - NBM;
        int l = tb3 / 1792, n = tb3 % 1792;
        d_biasH[tb3] = (n < 1024) ? tb[l * 1024 + n] : gbr[l * 768 + (n - 1024)];
    }
}

__global__ void prep_pe_kernel() {
    int idx = blockIdx.x * blockDim.x + threadIdx.x;
    if (idx >= 513 * 256) return;
    int p = idx >> 8, i = idx & 255;
    float v = 0.0f;
    if (p > 0) {
        float div = powf(10000.0f, (2.0f * (float)i) / 256.0f);
        float ang = (float)(p - 1) / div;
        v = (i & 1) ? cosf(ang) : sinf(ang);
    }
    d_pe[idx] = v;
}

// ===================== init: h = embed + pe, also fragment layout ===========
__global__ void init_h_kernel(const int* __restrict__ nodes,
                              const float* __restrict__ embed) {
    int idx = blockIdx.x * blockDim.x + threadIdx.x;
    if (idx >= NN * 64) return;
    int n = idx >> 6;
    int c = (idx & 63) * 4;
    int tok = nodes[n];
    int pos = nodes[NN + n];
    int p = pos < 512 ? pos : 512;
    float4 e = *(const float4*)(embed + (size_t)tok * 256 + c);
    float4 pe = *(const float4*)(d_pe + (size_t)p * 256 + c);
    float4 o = make_float4(e.x + pe.x, e.y + pe.y, e.z + pe.z, e.w + pe.w);
    *(float4*)&d_h[(size_t)n * 256 + c] = o;
    store_frag(d_hp, n, c, o.x, o.y, o.z, o.w);
}

// ===================== fp16 mma GEMM (R12 + smem-staged epilogue) ===========
__device__ __forceinline__ void mma16816(float* d, uint32_t a0, uint32_t a1,
                                         uint32_t a2, uint32_t a3,
                                         uint32_t b0, uint32_t b1) {
    asm volatile(
        "mma.sync.aligned.m16n8k16.row.col.f32.f16.f16.f32 "
        "{%0,%1,%2,%3}, {%4,%5,%6,%7}, {%8,%9}, {%0,%1,%2,%3};"
        : "+f"(d[0]), "+f"(d[1]), "+f"(d[2]), "+f"(d[3])
        : "r"(a0), "r"(a1), "r"(a2), "r"(a3), "r"(b0), "r"(b1));
}

#define STAGE_LD 136   // halves per staged row (conflict-free)

// 256 threads = 4x2 warps, warp tile 32(M) x 64(N). CTA tile 128x128.
// B tile (64KB) staged in smem; A register double-buffered LDG.
// Epilogue: acc -> smem stage (reusing sB) -> coalesced STG.128.
__global__ __launch_bounds__(256, 2)
void gemm_h16(const uint4* __restrict__ Ap, const uint4* __restrict__ Bp,
              const float* __restrict__ bias,
              __half* __restrict__ C1, int ldC1, int split,
              __half* __restrict__ C2, int ldC2, int J2tot) {
    extern __shared__ uint4 sB[];   // [16][8][32] = 64KB
    const int tid  = threadIdx.x;
    const int lane = tid & 31;
    const int wid  = tid >> 5;
    const int wr = wid & 3;
    const int wc = wid >> 2;
    const int mBase = blockIdx.x * 128;
    const int colBase = blockIdx.y * 128;
    const int i0 = blockIdx.x * 8 + wr * 2;
    const int j2cta = blockIdx.y * 8;

    const uint32_t sBu = smem_u32(sB);
#pragma unroll
    for (int i = 0; i < 16; i++) {
        int s_idx = tid + i * 256;
        int kk = s_idx >> 8;
        int rem = s_idx & 255;
        const uint4* src = Bp + (((size_t)(kk * J2tot + j2cta)) << 5) + rem;
        asm volatile("cp.async.cg.shared.global [%0], [%1], 16;"
                     :: "r"(sBu + s_idx * 16), "l"(src));
    }
    asm volatile("cp.async.commit_group;" ::: "memory");

    uint4 av[2];
#pragma unroll
    for (int m = 0; m < 2; m++)
        av[m] = Ap[((size_t)((i0 + m) * 16) * 32) + lane];

    float acc[2][8][4];
#pragma unroll
    for (int mi = 0; mi < 2; mi++)
#pragma unroll
        for (int j = 0; j < 8; j++)
#pragma unroll
            for (int r = 0; r < 4; r++) acc[mi][j][r] = 0.f;

    asm volatile("cp.async.wait_group 0;" ::: "memory");
    __syncthreads();

#pragma unroll
    for (int kk = 0; kk < 16; kk++) {
        uint4 av2[2];
        if (kk < 15) {
#pragma unroll
            for (int m = 0; m < 2; m++)
                av2[m] = Ap[((size_t)((i0 + m) * 16 + kk + 1) * 32) + lane];
        }
        uint4 bq[4];
#pragma unroll
        for (int q = 0; q < 4; q++)
            bq[q] = sB[(kk * 8 + wc * 4 + q) * 32 + lane];
#pragma unroll
        for (int mi = 0; mi < 2; mi++) {
#pragma unroll
            for (int q = 0; q < 4; q++) {
                mma16816(acc[mi][q * 2 + 0], av[mi].x, av[mi].y, av[mi].z,
                         av[mi].w, bq[q].x, bq[q].y);
                mma16816(acc[mi][q * 2 + 1], av[mi].x, av[mi].y, av[mi].z,
                         av[mi].w, bq[q].z, bq[q].w);
            }
        }
        if (kk < 15) {
#pragma unroll
            for (int m = 0; m < 2; m++) av[m] = av2[m];
        }
    }

    // ---- epilogue: stage in smem (reuse sB), then coalesced STG.128 ----
    __syncthreads();                     // all warps done reading sB
    __half* stage = (__half*)sB;         // [128][STAGE_LD]
#pragma unroll
    for (int mi = 0; mi < 2; mi++) {
        int r0 = wr * 32 + mi * 16 + (lane >> 2);
#pragma unroll
        for (int j = 0; j < 8; j++) {
            int col = wc * 64 + j * 8 + (lane & 3) * 2;
            float bx = bias[colBase + col], by = bias[colBase + col + 1];
            *(__half2*)&stage[r0 * STAGE_LD + col] =
                __floats2half2_rn(acc[mi][j][0] + bx, acc[mi][j][1] + by);
            *(__half2*)&stage[(r0 + 8) * STAGE_LD + col] =
                __floats2half2_rn(acc[mi][j][2] + bx, acc[mi][j][3] + by);
        }
    }
    __syncthreads();
    __half* Cout;
    int ld, ccBase;
    if (colBase < split) { Cout = C1; ld = ldC1; ccBase = colBase; }
    else                 { Cout = C2; ld = ldC2; ccBase = colBase - split; }
#pragma unroll
    for (int it = 0; it < 8; it++) {
        int idx = tid + it * 256;
        int row = idx >> 4, qq = idx & 15;
        uint4 v = *(uint4*)&stage[row * STAGE_LD + qq * 8];
        *(uint4*)(Cout + (size_t)(mBase + row) * ld + ccBase + qq * 8) = v;
    }
}

#define GEMM_SMEM 65536

// ===================== zero / scatter / permute / gru =======================
__global__ void zero4_kernel(uint4* __restrict__ p, int n) {
    int i = blockIdx.x * blockDim.x + threadIdx.x;
    if (i < n) p[i] = make_uint4(0u, 0u, 0u, 0u);
}

// vectorized fp16 RED scatter into row-major msgs: 1 op/lane, 32 ops/edge
__global__ void scatter_kernel(const int* __restrict__ edges) {
    int idx = blockIdx.x * blockDim.x + threadIdx.x;
    int e = idx >> 5;
    if (e >= NE) return;
    int lane = idx & 31;
    int et  = edges[e * 3 + 0];
    int src = edges[e * 3 + 1];
    int tgt = edges[e * 3 + 2];
    const uint4 v = *(const uint4*)&d_trans[((size_t)src * 4 + et) * HH + lane * 8];
    __half* dst = &d_msgsh[(size_t)tgt * HH + lane * 8];
    asm volatile("red.global.add.noftz.v4.f16x2 [%0], {%1,%2,%3,%4};"
                 :: "l"(dst), "r"(v.x), "r"(v.y), "r"(v.z), "r"(v.w)
                 : "memory");
}

// pure word-shuffle permute: row-major fp16 -> mma fragment layout
__global__ void permute_h_kernel() {
    int t = blockIdx.x * blockDim.x + threadIdx.x;
    if (t >= MT16 * 512) return;
    int lane = t & 31;
    int kk = (t >> 5) & 15;
    int i  = t >> 9;
    int r = lane >> 2, c2 = (lane & 3) * 2;
    int row0 = i * 16 + r, row1 = row0 + 8;
    int col0 = kk * 16 + c2;
    uint4 o = make_uint4(0u, 0u, 0u, 0u);
    if (row0 < NN) {
        o.x = *(const uint32_t*)&d_msgsh[(size_t)row0 * 256 + col0];
        o.z = *(const uint32_t*)&d_msgsh[(size_t)row0 * 256 + col0 + 8];
    }
    if (row1 < NN) {
        o.y = *(const uint32_t*)&d_msgsh[(size_t)row1 * 256 + col0];
        o.w = *(const uint32_t*)&d_msgsh[(size_t)row1 * 256 + col0 + 8];
    }
    d_msgsp[t] = o;
}

__device__ __forceinline__ float sigm(float x) { return 1.0f / (1.0f + expf(-x)); }

__global__ void gru_kernel(int write_hp) {
    int idx = blockIdx.x * blockDim.x + threadIdx.x;
    if (idx >= NN * 64) return;
    int n = idx >> 6;
    int c = (idx & 63) * 4;
    const __half2* g1 = (const __half2*)&d_g1h[(size_t)n * 768];
    const __half2* g2 = (const __half2*)&d_g2h[(size_t)n * 768];
    int c2 = c >> 1;
    float2 xz0 = __half22float2(g1[c2]),       xz1 = __half22float2(g1[c2 + 1]);
    float2 xr0 = __half22float2(g1[128 + c2]), xr1 = __half22float2(g1[128 + c2 + 1]);
    float2 xh0 = __half22float2(g1[256 + c2]), xh1 = __half22float2(g1[256 + c2 + 1]);
    float2 hz0 = __half22float2(g2[c2]),       hz1 = __half22float2(g2[c2 + 1]);
    float2 hr0 = __half22float2(g2[128 + c2]), hr1 = __half22float2(g2[128 + c2 + 1]);
    float2 hh0 = __half22float2(g2[256 + c2]), hh1 = __half22float2(g2[256 + c2 + 1]);
    float4 ho = *(float4*)&d_h[(size_t)n * 256 + c];
    float xzv[4] = {xz0.x, xz0.y, xz1.x, xz1.y};
    float xrv[4] = {xr0.x, xr0.y, xr1.x, xr1.y};
    float xhv[4] = {xh0.x, xh0.y, xh1.x, xh1.y};
    float hzv[4] = {hz0.x, hz0.y, hz1.x, hz1.y};
    float hrv[4] = {hr0.x, hr0.y, hr1.x, hr1.y};
    float hhv[4] = {hh0.x, hh0.y, hh1.x, hh1.y};
    float hov[4] = {ho.x, ho.y, ho.z, ho.w};
    float o[4];
#pragma unroll
    for (int q = 0; q < 4; q++) {
        float z = sigm(xzv[q] + hzv[q]);
        float r = sigm(xrv[q] + hrv[q]);
        float cand = tanhf(xhv[q] + r * hhv[q]);
        o[q] = z * hov[q] + (1.0f - z) * cand;
    }
    *(float4*)&d_h[(size_t)n * 256 + c] = make_float4(o[0], o[1], o[2], o[3]);
    if (write_hp) store_frag(d_hp, n, c, o[0], o[1], o[2], o[3]);
}

// ===================== readout ==============================================
__global__ void head_kernel(const float* __restrict__ gateW,
                            const float* __restrict__ gateb,
                            const float* __restrict__ outW,
                            const float* __restrict__ outb) {
    int gidx = blockIdx.x * blockDim.x + threadIdx.x;
    int warp = gidx >> 5;
    int lane = gidx & 31;
    if (warp >= NN) return;
    float g = 0.f, o0 = 0.f, o1 = 0.f;
    for (int c = lane; c < HH; c += 32) {
        float hv = d_h[(size_t)warp * HH + c];
        g  += hv * gateW[c];
        o0 += hv * outW[c * 2 + 0];
        o1 += hv * outW[c * 2 + 1];
    }
#pragma unroll
    for (int off = 16; off; off >>= 1) {
        g  += __shfl_down_sync(0xffffffffu, g,  off);
        o0 += __shfl_down_sync(0xffffffffu, o0, off);
        o1 += __shfl_down_sync(0xffffffffu, o1, off);
    }
    if (lane == 0) {
        d_gate[warp] = g + gateb[0];
        d_out2[warp * 2 + 0] = o0 + outb[0];
        d_out2[warp * 2 + 1] = o1 + outb[1];
    }
}

__global__ void max1_kernel() {
    __shared__ float s[256];
    float m = -INFINITY;
    for (int i = blockIdx.x * 256 + threadIdx.x; i < NN; i += gridDim.x * 256)
        m = fmaxf(m, d_gate[i]);
    s[threadIdx.x] = m;
    __syncthreads();
    for (int o = 128; o; o >>= 1) {
        if (threadIdx.x < o) s[threadIdx.x] = fmaxf(s[threadIdx.x], s[threadIdx.x + o]);
        __syncthreads();
    }
    if (threadIdx.x == 0) d_partial[blockIdx.x] = s[0];
}

__global__ void max2_kernel(int nb) {
    __shared__ float s[256];
    float m = (threadIdx.x < nb) ? d_partial[threadIdx.x] : -INFINITY;
    s[threadIdx.x] = m;
    __syncthreads();
    for (int o = 128; o; o >>= 1) {
        if (threadIdx.x < o) s[threadIdx.x] = fmaxf(s[threadIdx.x], s[threadIdx.x + o]);
        __syncthreads();
    }
    if (threadIdx.x == 0) d_gmax = s[0];
}

__global__ void cum_kernel(const int* __restrict__ gs) {
    if (threadIdx.x == 0 && blockIdx.x == 0) {
        int c = 0;
        d_cum[0] = 0;
        for (int i = 0; i < GG; i++) { c += gs[i]; d_cum[i + 1] = c; }
    }
}

__global__ void zero_sp_kernel() {
    int i = threadIdx.x;
    if (i < GG) d_S[i] = 0.f;
    if (i < GG * 2) d_P[i] = 0.f;
}

__global__ void accum_kernel() {
    int n = blockIdx.x * blockDim.x + threadIdx.x;
    if (n >= NN) return;
    int lo = 0, hi = GG;
    while (hi - lo > 1) {
        int mid = (lo + hi) >> 1;
        if (d_cum[mid] <= n) lo = mid; else hi = mid;
    }
    int seg = lo;
    float e = expf(d_gate[n] - d_gmax);
    atomicAdd(&d_S[seg], e);
    atomicAdd(&d_P[seg * 2 + 0], e * d_out2[n * 2 + 0]);
    atomicAdd(&d_P[seg * 2 + 1], e * d_out2[n * 2 + 1]);
}

__global__ void final_kernel(float* __restrict__ out) {
    int i = threadIdx.x;
    if (i < GG * 2) out[i] = d_P[i] / (d_S[i >> 1] + 1e-16f);
}

// ===================== host orchestration ===================================
extern "C" void kernel_launch(void* const* d_in, const int* in_sizes, int n_in,
                              void* d_out, int out_size) {
    const int*   nodes       = (const int*)d_in[0];
    const int*   graph_sizes = (const int*)d_in[1];
    const int*   edges       = (const int*)d_in[2];
    const float* embed       = (const float*)d_in[3];
    const float* tw          = (const float*)d_in[4];
    const float* tb          = (const float*)d_in[5];
    const float* gruW        = (const float*)d_in[6];
    const float* gruU        = (const float*)d_in[7];
    const float* gbi         = (const float*)d_in[8];
    const float* gbr         = (const float*)d_in[9];
    const float* gateW       = (const float*)d_in[10];
    const float* gateb       = (const float*)d_in[11];
    const float* outW        = (const float*)d_in[12];
    const float* outb        = (const float*)d_in[13];
    float* out = (float*)d_out;

    float *p_biasH;
    __half *p_trans, *p_msgsh, *p_g1h, *p_g2h;
    uint4 *p_hp, *p_msgsp, *p_BH, *p_BM;
    cudaGetSymbolAddress((void**)&p_trans, d_trans);
    cudaGetSymbolAddress((void**)&p_msgsh, d_msgsh);
    cudaGetSymbolAddress((void**)&p_g1h, d_g1h);
    cudaGetSymbolAddress((void**)&p_g2h, d_g2h);
    cudaGetSymbolAddress((void**)&p_biasH, d_biasH);
    cudaGetSymbolAddress((void**)&p_hp, d_hp);
    cudaGetSymbolAddress((void**)&p_msgsp, d_msgsp);
    cudaGetSymbolAddress((void**)&p_BH, d_BH);
    cudaGetSymbolAddress((void**)&p_BM, d_BM);

    cudaFuncSetAttribute(gemm_h16, cudaFuncAttributeMaxDynamicSharedMemorySize,
                         GEMM_SMEM);

    // launch 1: merged weight prep; 2: pe table; 3: init; 4: gemm1 (profiled)
    prep_weights_kernel<<<(NPREP + 255) / 256, 256>>>(tw, gruU, gruW, tb, gbr);
    prep_pe_kernel<<<(513 * 256 + 255) / 256, 256>>>();
    init_h_kernel<<<(NN * 64 + 255) / 256, 256>>>(nodes, embed);

    const int layers[4] = {0, 0, 0, 1};
    const int gridM = NN_PAD / 128;               // 782
    const int msgshN = NN * HH * 2 / 16;          // uint4 count
    const int permN = MT16 * 512;

    for (int s = 0; s < 4; s++) {
        int l = layers[s];
        // fused: h @ [typeW(1024 -> trans fp16) | gruU(768 -> g2h fp16)]
        gemm_h16<<<dim3(gridM, 14), 256, GEMM_SMEM>>>(
            p_hp, p_BH + (size_t)l * 16 * J2H * 32, p_biasH + l * 1792,
            p_trans, 1024, 1024, p_g2h, 768, J2H);
        zero4_kernel<<<(msgshN + 255) / 256, 256>>>((uint4*)p_msgsh, msgshN);
        scatter_kernel<<<(size_t)NE * 32 / 256, 256>>>(edges);
        permute_h_kernel<<<(permN + 255) / 256, 256>>>();
        gemm_h16<<<dim3(gridM, 6), 256, GEMM_SMEM>>>(
            p_msgsp, p_BM + (size_t)l * 16 * J2M * 32, gbi + l * 768,
            p_g1h, 768, 1 << 28, p_g1h, 768, J2M);
        gru_kernel<<<(NN * 64 + 255) / 256, 256>>>(s < 3 ? 1 : 0);
    }

    head_kernel<<<(NN * 32 + 255) / 256, 256>>>(gateW, gateb, outW, outb);
    max1_kernel<<<256, 256>>>();
    max2_kernel<<<1, 256>>>(256);
    cum_kernel<<<1, 1>>>(graph_sizes);
    zero_sp_kernel<<<1, 256>>>();
    accum_kernel<<<(NN + 255) / 256, 256>>>();
    final_kernel<<<1, 256>>>(out);
}